// round 13
// baseline (speedup 1.0000x reference)
#include <cuda_runtime.h>
#include <cuda_bf16.h>
#include <math.h>
#include <stdint.h>

#define N_NODES 50000
#define N_EDGES 1600000
#define N_GRAPHS 64
#define DELTA_C 2.5749f
#define BN_EPS 1e-5f
#define NB_SCAN 49

// ---------------- scratch ----------------
__device__ float g_featA[N_NODES * 64];
__device__ float g_featB[N_NODES * 64];
__device__ __nv_bfloat16 g_aggrHi[(size_t)N_NODES * 256];
__device__ __nv_bfloat16 g_aggrLo[(size_t)N_NODES * 256];
__device__ int   g_deg[N_NODES];
__device__ int   g_rowptr[N_NODES + 1];
__device__ int   g_cursor[N_NODES];
__device__ int   g_csrc[N_EDGES];
__device__ int   g_scanstate[64];
__device__ int   g_gcnt[64];
__device__ __nv_bfloat16 g_Whi[3][192 * 256];   // [p*64+o][k]
__device__ __nv_bfloat16 g_Wlo[3][192 * 256];
__device__ __nv_bfloat16 g_W1hi[3][4096], g_W1lo[3][4096];  // [o][k]
__device__ __nv_bfloat16 g_W2hi[3][4096], g_W2lo[3][4096];
__device__ float g_colsum[3][64];
__device__ float g_colsq[3][64];
__device__ float g_pool[N_GRAPHS * 64];

// smem layout for k_mlp (dynamic):
#define SA_STRIDE 264
#define SW_STRIDE 72
#define AHI_OFF 0                  // 128*264*2 = 67584
#define ALO_OFF 67584              // ends 135168
#define WHI_OFF 135168             // 27648 region
#define WLO_OFF 162816
#define MLP_SMEM 190464
// phase-2/3 overlays inside dead A region (stride 72 planes, 128x72x2 = 18432 B):
#define H_HI 0
#define H_LO 18432
#define T_HI 36864
#define T_LO 55296
#define SCOL_OFF 73728             // 128 f32
#define POOL_OFF 74240             // 4096 f32 (layer 2 only)

// scan state flags (value packed in low 30 bits)
#define FLAG_AGG (1 << 30)
#define FLAG_PRE (2 << 30)
#define VAL_MASK ((1 << 30) - 1)

// ---------------- warp mma ----------------
__device__ __forceinline__ void mma_bf16(float* acc, uint32_t a0, uint32_t a1,
                                         uint32_t a2, uint32_t a3,
                                         uint32_t b0, uint32_t b1) {
    asm volatile("mma.sync.aligned.m16n8k16.row.col.f32.bf16.bf16.f32 "
        "{%0,%1,%2,%3}, {%4,%5,%6,%7}, {%8,%9}, {%0,%1,%2,%3};"
        : "+f"(acc[0]), "+f"(acc[1]), "+f"(acc[2]), "+f"(acc[3])
        : "r"(a0), "r"(a1), "r"(a2), "r"(a3), "r"(b0), "r"(b1));
}

__device__ __forceinline__ __nv_bfloat162 bf16_split(float a, float b,
                                                     __nv_bfloat162& lo) {
    __nv_bfloat162 hi;
    hi.x = __float2bfloat16(a);
    hi.y = __float2bfloat16(b);
    lo.x = __float2bfloat16(a - __bfloat162float(hi.x));
    lo.y = __float2bfloat16(b - __bfloat162float(hi.y));
    return hi;
}

// ---------------- weight prep (all 3 layers) + zero deg/gcnt/scanstate ----------------
__global__ void k_prep_all(const float* __restrict__ W3, const float* __restrict__ W9,
                           const float* __restrict__ W15) {
    int gi = blockIdx.x * blockDim.x + threadIdx.x;
    if (gi < N_NODES) g_deg[gi] = 0;
    if (gi < 64) { g_gcnt[gi] = 0; g_scanstate[gi] = 0; }
    int layer = gi / 49152;
    int i = gi % 49152;
    if (layer < 3) {
        const float* mlpW = (layer == 0) ? W3 : (layer == 1) ? W9 : W15;
        int j = i >> 8, k = i & 255;
        int p = j >> 6, o = j & 63;
        float w = mlpW[o * 768 + p * 256 + k];
        __nv_bfloat16 hi = __float2bfloat16(w);
        __nv_bfloat16 lo = __float2bfloat16(w - __bfloat162float(hi));
        g_Whi[layer][i] = hi;
        g_Wlo[layer][i] = lo;
    }
}
__global__ void k_prep_small(const float* __restrict__ W1a, const float* __restrict__ W2a,
                             const float* __restrict__ W1b, const float* __restrict__ W2b,
                             const float* __restrict__ W1c, const float* __restrict__ W2c) {
    int gi = blockIdx.x * blockDim.x + threadIdx.x;
    int layer = gi >> 12, i = gi & 4095;
    if (layer < 3) {
        const float* W1 = (layer == 0) ? W1a : (layer == 1) ? W1b : W1c;
        const float* W2 = (layer == 0) ? W2a : (layer == 1) ? W2b : W2c;
        float w1 = W1[i], w2 = W2[i];           // [o][k] layout kept as-is
        __nv_bfloat16 h1 = __float2bfloat16(w1);
        g_W1hi[layer][i] = h1;
        g_W1lo[layer][i] = __float2bfloat16(w1 - __bfloat162float(h1));
        __nv_bfloat16 h2 = __float2bfloat16(w2);
        g_W2hi[layer][i] = h2;
        g_W2lo[layer][i] = __float2bfloat16(w2 - __bfloat162float(h2));
    }
}

// ---------------- CSR build (4 edges/thread, high occupancy) ----------------
__global__ void k_count(const int* __restrict__ dst) {
    int e4 = blockIdx.x * blockDim.x + threadIdx.x;
    if (e4 < N_EDGES / 4) {
        int4 d = *(const int4*)&dst[e4 * 4];
        atomicAdd(&g_deg[d.x], 1);
        atomicAdd(&g_deg[d.y], 1);
        atomicAdd(&g_deg[d.z], 1);
        atomicAdd(&g_deg[d.w], 1);
    }
}

// single-kernel decoupled-lookback scan: rowptr, cursor, pool/stat zero, graph histogram
__global__ void k_scan_fused(const int* __restrict__ batch) {
    __shared__ int s[1024];
    __shared__ int s_off;
    __shared__ int h[64];
    int t = threadIdx.x, b = blockIdx.x;
    int idx = b * 1024 + t;
    if (t < 64) h[t] = 0;
    int deg = (idx < N_NODES) ? g_deg[idx] : 0;
    s[t] = deg;
    __syncthreads();
    for (int d = 1; d < 1024; d <<= 1) {
        int add = (t >= d) ? s[t - d] : 0;
        __syncthreads();
        s[t] += add;
        __syncthreads();
    }
    if (t == 0) {
        int total = s[1023];
        atomicExch(&g_scanstate[b], FLAG_AGG | total);   // publish aggregate
        int run = 0;
        for (int j = b - 1; j >= 0;) {
            int st = atomicAdd(&g_scanstate[j], 0);
            if (st == 0) continue;                        // not yet published
            if (st & FLAG_PRE) { run += st & VAL_MASK; break; }
            run += st & VAL_MASK;
            j--;
        }
        atomicExch(&g_scanstate[b], FLAG_PRE | (run + total));
        s_off = run;
    }
    __syncthreads();
    int off = s_off;
    if (idx < N_NODES) {
        int inc = off + s[t];
        g_rowptr[idx + 1] = inc;
        g_cursor[idx] = inc - deg;
        atomicAdd(&h[batch[idx]], 1);
    }
    if (idx == 0) g_rowptr[0] = 0;
    if (idx < N_GRAPHS * 64) g_pool[idx] = 0.f;
    if (idx < 192) {
        g_colsum[idx >> 6][idx & 63] = 0.f;
        g_colsq[idx >> 6][idx & 63] = 0.f;
    }
    __syncthreads();
    if (t < 64 && h[t]) atomicAdd(&g_gcnt[t], h[t]);
}

__global__ void k_fill(const int* __restrict__ src, const int* __restrict__ dst) {
    int e4 = blockIdx.x * blockDim.x + threadIdx.x;
    if (e4 < N_EDGES / 4) {
        int4 s = *(const int4*)&src[e4 * 4];
        int4 d = *(const int4*)&dst[e4 * 4];
        g_csrc[atomicAdd(&g_cursor[d.x], 1)] = s.x;
        g_csrc[atomicAdd(&g_cursor[d.y], 1)] = s.y;
        g_csrc[atomicAdd(&g_cursor[d.z], 1)] = s.z;
        g_csrc[atomicAdd(&g_cursor[d.w], 1)] = s.w;
    }
}

// ---------------- aggregation: warp/node CSR gather, dual accumulators,
// software-pipelined index loads, fused BN affine, bf16-split out ----------------
__global__ __launch_bounds__(256) void k_aggr(const float* __restrict__ xf,
                                              const float* __restrict__ gg,
                                              const float* __restrict__ bb,
                                              int prevLayer) {
    int warp = (blockIdx.x * blockDim.x + threadIdx.x) >> 5;
    int lane = threadIdx.x & 31;
    if (warp >= N_NODES) return;

    float a0 = 1.f, b0 = 0.f, a1 = 1.f, b1 = 0.f;
    if (gg) {
        int c = 2 * lane;
        float m = g_colsum[prevLayer][c] * (1.f / N_NODES);
        float vv = g_colsq[prevLayer][c] * (1.f / N_NODES) - m * m;
        a0 = gg[c] * rsqrtf(vv + BN_EPS);
        b0 = bb[c] - m * a0;
        m = g_colsum[prevLayer][c + 1] * (1.f / N_NODES);
        vv = g_colsq[prevLayer][c + 1] * (1.f / N_NODES) - m * m;
        a1 = gg[c + 1] * rsqrtf(vv + BN_EPS);
        b1 = bb[c + 1] - m * a1;
    }

    int beg = g_rowptr[warp];
    int end = g_rowptr[warp + 1];

    // dual accumulator banks (even/odd edges) to halve dependent-chain depth
    float sa0 = 0.f, sa1 = 0.f, qa0 = 0.f, qa1 = 0.f;
    float sb0 = 0.f, sb1 = 0.f, qb0 = 0.f, qb1 = 0.f;
    float ma0 = -INFINITY, ma1 = -INFINITY;
    float mb0 = -INFINITY, mb1 = -INFINITY;

    // pipelined edge-index load (every node has >= 1 edge, clamp is safe)
    int eidx = beg + lane;
    int e = g_csrc[(eidx < end) ? eidx : (end - 1)];

    int j = beg;
    for (; j + 32 <= end; j += 32) {
        int e_cur = e;
        int nj = j + 32;
        if (nj < end) {
            int ni = nj + lane;
            e = g_csrc[(ni < end) ? ni : (end - 1)];
        }
#pragma unroll
        for (int i = 0; i < 32; i += 2) {
            int sA = __shfl_sync(0xffffffffu, e_cur, i);
            int sB = __shfl_sync(0xffffffffu, e_cur, i + 1);
            float2 vA = *(const float2*)&xf[sA * 64 + 2 * lane];
            float2 vB = *(const float2*)&xf[sB * 64 + 2 * lane];
            float vA0 = fmaf(vA.x, a0, b0);
            float vA1 = fmaf(vA.y, a1, b1);
            float vB0 = fmaf(vB.x, a0, b0);
            float vB1 = fmaf(vB.y, a1, b1);
            sa0 += vA0; sa1 += vA1;
            sb0 += vB0; sb1 += vB1;
            qa0 = fmaf(vA0, vA0, qa0); qa1 = fmaf(vA1, vA1, qa1);
            qb0 = fmaf(vB0, vB0, qb0); qb1 = fmaf(vB1, vB1, qb1);
            ma0 = fmaxf(ma0, vA0); ma1 = fmaxf(ma1, vA1);
            mb0 = fmaxf(mb0, vB0); mb1 = fmaxf(mb1, vB1);
        }
    }
    int nrem = end - j;
    for (int i = 0; i < nrem; i++) {
        int sidx = __shfl_sync(0xffffffffu, e, i);
        float2 v = *(const float2*)&xf[sidx * 64 + 2 * lane];
        float v0 = fmaf(v.x, a0, b0);
        float v1 = fmaf(v.y, a1, b1);
        sa0 += v0; sa1 += v1;
        qa0 = fmaf(v0, v0, qa0); qa1 = fmaf(v1, v1, qa1);
        ma0 = fmaxf(ma0, v0); ma1 = fmaxf(ma1, v1);
    }

    float s0 = sa0 + sb0, s1 = sa1 + sb1;
    float q0 = qa0 + qb0, q1 = qa1 + qb1;
    float m0 = fmaxf(ma0, mb0), m1 = fmaxf(ma1, mb1);

    float cnt = (float)(end - beg);
    float inv = 1.0f / cnt;
    float mean0 = s0 * inv, mean1 = s1 * inv;
    float var0 = fmaxf(q0 * inv - mean0 * mean0, 0.f);
    float var1 = fmaxf(q1 * inv - mean1 * mean1, 0.f);

    __nv_bfloat16* ah = g_aggrHi + (size_t)warp * 256;
    __nv_bfloat16* al = g_aggrLo + (size_t)warp * 256;
    __nv_bfloat162 lo, hi;
    hi = bf16_split(s0, s1, lo);
    *(__nv_bfloat162*)&ah[2 * lane] = hi;       *(__nv_bfloat162*)&al[2 * lane] = lo;
    hi = bf16_split(m0, m1, lo);
    *(__nv_bfloat162*)&ah[64 + 2 * lane] = hi;  *(__nv_bfloat162*)&al[64 + 2 * lane] = lo;
    hi = bf16_split(mean0, mean1, lo);
    *(__nv_bfloat162*)&ah[128 + 2 * lane] = hi; *(__nv_bfloat162*)&al[128 + 2 * lane] = lo;
    hi = bf16_split(var0, var1, lo);
    *(__nv_bfloat162*)&ah[192 + 2 * lane] = hi; *(__nv_bfloat162*)&al[192 + 2 * lane] = lo;
}

// ---------------- fused MLP: all three GEMMs on HMMA ----------------
__global__ __launch_bounds__(256) void k_mlp(const float* __restrict__ x,
                                             const float* __restrict__ mlpb,
                                             const float* __restrict__ b1v,
                                             const float* __restrict__ b2v,
                                             float* __restrict__ out, int layer,
                                             const float* __restrict__ ggP,
                                             const float* __restrict__ bbP,
                                             const int* __restrict__ batch) {
    extern __shared__ __align__(16) char smem[];
    __nv_bfloat16* sAhi = (__nv_bfloat16*)(smem + AHI_OFF);
    __nv_bfloat16* sAlo = (__nv_bfloat16*)(smem + ALO_OFF);
    __nv_bfloat16* sWhi = (__nv_bfloat16*)(smem + WHI_OFF);
    __nv_bfloat16* sWlo = (__nv_bfloat16*)(smem + WLO_OFF);
    __nv_bfloat16* sHhi = (__nv_bfloat16*)(smem + H_HI);
    __nv_bfloat16* sHlo = (__nv_bfloat16*)(smem + H_LO);
    __nv_bfloat16* sThi = (__nv_bfloat16*)(smem + T_HI);
    __nv_bfloat16* sTlo = (__nv_bfloat16*)(smem + T_LO);
    float* scol  = (float*)(smem + SCOL_OFF);
    float* sPool = (float*)(smem + POOL_OFF);

    int t = threadIdx.x, lane = t & 31, w = t >> 5;
    int g = lane >> 2, tq = lane & 3;
    int tileBase = blockIdx.x * 128;
    int mb = (w & 3) * 32, nb = (w >> 2) * 32;

    // ---- A copy: pre-split planes -> smem ----
    {
        int r = t >> 1;
        int half = (t & 1) * 128;
        int node = tileBase + r;
        uint4* dHi = (uint4*)(sAhi + r * SA_STRIDE + half);
        uint4* dLo = (uint4*)(sAlo + r * SA_STRIDE + half);
        if (node < N_NODES) {
            const uint4* sHi = (const uint4*)(g_aggrHi + (size_t)node * 256 + half);
            const uint4* sLo = (const uint4*)(g_aggrLo + (size_t)node * 256 + half);
#pragma unroll
            for (int c = 0; c < 16; c++) { dHi[c] = sHi[c]; dLo[c] = sLo[c]; }
        } else {
            uint4 z = make_uint4(0, 0, 0, 0);
#pragma unroll
            for (int c = 0; c < 16; c++) { dHi[c] = z; dLo[c] = z; }
        }
    }

    float acc[2][4][3][4];
#pragma unroll
    for (int mi = 0; mi < 2; mi++)
#pragma unroll
        for (int q = 0; q < 4; q++)
#pragma unroll
            for (int p = 0; p < 3; p++)
#pragma unroll
                for (int i = 0; i < 4; i++) acc[mi][q][p][i] = 0.f;

    const __nv_bfloat16* gwhi = g_Whi[layer];
    const __nv_bfloat16* gwlo = g_Wlo[layer];

    for (int kc = 0; kc < 256; kc += 64) {
        __syncthreads();
        for (int idx = t; idx < 1536; idx += 256) {
            int j = idx >> 3, kk = (idx & 7) * 8;
            *(float4*)&sWhi[j * SW_STRIDE + kk] = *(const float4*)&gwhi[j * 256 + kc + kk];
            *(float4*)&sWlo[j * SW_STRIDE + kk] = *(const float4*)&gwlo[j * 256 + kc + kk];
        }
        __syncthreads();
#pragma unroll
        for (int pass = 0; pass < 3; pass++) {
            const __nv_bfloat16* A = (pass == 2) ? sAlo : sAhi;
            const __nv_bfloat16* B = (pass == 1) ? sWlo : sWhi;
#pragma unroll
            for (int ks = 0; ks < 4; ks++) {
                int ka = kc + ks * 16 + 2 * tq;
                int kw = ks * 16 + 2 * tq;
                uint32_t a[2][4];
#pragma unroll
                for (int mi = 0; mi < 2; mi++) {
                    const __nv_bfloat16* ar0 = A + (mb + mi * 16 + g) * SA_STRIDE + ka;
                    const __nv_bfloat16* ar1 = ar0 + 8 * SA_STRIDE;
                    a[mi][0] = *(const uint32_t*)ar0;
                    a[mi][1] = *(const uint32_t*)ar1;
                    a[mi][2] = *(const uint32_t*)(ar0 + 8);
                    a[mi][3] = *(const uint32_t*)(ar1 + 8);
                }
#pragma unroll
                for (int q = 0; q < 4; q++)
#pragma unroll
                    for (int p = 0; p < 3; p++) {
                        const __nv_bfloat16* br = B + (nb + q * 8 + p * 64 + g) * SW_STRIDE + kw;
                        uint32_t b0 = *(const uint32_t*)br;
                        uint32_t b1 = *(const uint32_t*)(br + 8);
                        mma_bf16(acc[0][q][p], a[0][0], a[0][1], a[0][2], a[0][3], b0, b1);
                        mma_bf16(acc[1][q][p], a[1][0], a[1][1], a[1][2], a[1][3], b0, b1);
                    }
            }
        }
    }
    __syncthreads();   // main mma done; A region + W region reusable

    // ---- residual BN affine (layer>0) ----
    float ra[4][2], rb[4][2];
#pragma unroll
    for (int q = 0; q < 4; q++)
#pragma unroll
        for (int j = 0; j < 2; j++) {
            float a = 1.f, b = 0.f;
            if (ggP) {
                int c = nb + q * 8 + 2 * tq + j;
                float m = g_colsum[layer - 1][c] * (1.f / N_NODES);
                float vv = g_colsq[layer - 1][c] * (1.f / N_NODES) - m * m;
                a = ggP[c] * rsqrtf(vv + BN_EPS);
                b = bbP[c] - m * a;
            }
            ra[q][j] = a; rb[q][j] = b;
        }

    // ---- stream W1 planes, zero scol / sPool, split h into planes ----
    for (int i = t; i < 512; i += 256) {
        int j = i >> 3, kk = (i & 7) * 8;
        *(float4*)&sWhi[j * SW_STRIDE + kk] = *(const float4*)&g_W1hi[layer][j * 64 + kk];
        *(float4*)&sWlo[j * SW_STRIDE + kk] = *(const float4*)&g_W1lo[layer][j * 64 + kk];
    }
    if (t < 128) scol[t] = 0.f;
    if (layer == 2)
        for (int i = t; i < 4096; i += 256) sPool[i] = 0.f;

#pragma unroll
    for (int mi = 0; mi < 2; mi++)
#pragma unroll
        for (int hh = 0; hh < 2; hh++) {
            int r = mb + mi * 16 + hh * 8 + g;
            int node = tileBase + r;
            bool valid = node < N_NODES;
            float cnt = valid ? (float)g_deg[node] : 1.f;
            float s1 = cnt * (1.f / DELTA_C);
            float s2 = DELTA_C / cnt;
#pragma unroll
            for (int q = 0; q < 4; q++) {
                int c0 = nb + q * 8 + 2 * tq;
                float f0 = acc[mi][q][0][2 * hh] + s1 * acc[mi][q][1][2 * hh]
                         + s2 * acc[mi][q][2][2 * hh] + mlpb[c0];
                float f1 = acc[mi][q][0][2 * hh + 1] + s1 * acc[mi][q][1][2 * hh + 1]
                         + s2 * acc[mi][q][2][2 * hh + 1] + mlpb[c0 + 1];
                if (valid) {
                    float2 xv = *(const float2*)&x[node * 64 + c0];
                    f0 += fmaf(xv.x, ra[q][0], rb[q][0]);
                    f1 += fmaf(xv.y, ra[q][1], rb[q][1]);
                }
                __nv_bfloat162 lo, hi = bf16_split(f0, f1, lo);
                *(__nv_bfloat162*)&sHhi[r * SW_STRIDE + c0] = hi;
                *(__nv_bfloat162*)&sHlo[r * SW_STRIDE + c0] = lo;
            }
        }
    __syncthreads();

    // ---- phase 2: t1 = relu(h @ W1^T + b1) via HMMA (K=64) ----
    float acc2[2][4][4];
#pragma unroll
    for (int mi = 0; mi < 2; mi++)
#pragma unroll
        for (int q = 0; q < 4; q++)
#pragma unroll
            for (int i = 0; i < 4; i++) acc2[mi][q][i] = 0.f;
#pragma unroll
    for (int pass = 0; pass < 3; pass++) {
        const __nv_bfloat16* A = (pass == 2) ? sHlo : sHhi;
        const __nv_bfloat16* B = (pass == 1) ? sWlo : sWhi;
#pragma unroll
        for (int ks = 0; ks < 4; ks++) {
            int ka = ks * 16 + 2 * tq;
            uint32_t a[2][4];
#pragma unroll
            for (int mi = 0; mi < 2; mi++) {
                const __nv_bfloat16* ar0 = A + (mb + mi * 16 + g) * SW_STRIDE + ka;
                const __nv_bfloat16* ar1 = ar0 + 8 * SW_STRIDE;
                a[mi][0] = *(const uint32_t*)ar0;
                a[mi][1] = *(const uint32_t*)ar1;
                a[mi][2] = *(const uint32_t*)(ar0 + 8);
                a[mi][3] = *(const uint32_t*)(ar1 + 8);
            }
#pragma unroll
            for (int q = 0; q < 4; q++) {
                const __nv_bfloat16* br = B + (nb + q * 8 + g) * SW_STRIDE + ka;
                uint32_t b0 = *(const uint32_t*)br;
                uint32_t b1 = *(const uint32_t*)(br + 8);
                mma_bf16(acc2[0][q], a[0][0], a[0][1], a[0][2], a[0][3], b0, b1);
                mma_bf16(acc2[1][q], a[1][0], a[1][1], a[1][2], a[1][3], b0, b1);
            }
        }
    }
    __syncthreads();   // W1 reads done -> stream W2

    for (int i = t; i < 512; i += 256) {
        int j = i >> 3, kk = (i & 7) * 8;
        *(float4*)&sWhi[j * SW_STRIDE + kk] = *(const float4*)&g_W2hi[layer][j * 64 + kk];
        *(float4*)&sWlo[j * SW_STRIDE + kk] = *(const float4*)&g_W2lo[layer][j * 64 + kk];
    }
#pragma unroll
    for (int mi = 0; mi < 2; mi++)
#pragma unroll
        for (int hh = 0; hh < 2; hh++) {
            int r = mb + mi * 16 + hh * 8 + g;
#pragma unroll
            for (int q = 0; q < 4; q++) {
                int c0 = nb + q * 8 + 2 * tq;
                float v0 = fmaxf(acc2[mi][q][2 * hh] + b1v[c0], 0.f);
                float v1 = fmaxf(acc2[mi][q][2 * hh + 1] + b1v[c0 + 1], 0.f);
                __nv_bfloat162 lo, hi = bf16_split(v0, v1, lo);
                *(__nv_bfloat162*)&sThi[r * SW_STRIDE + c0] = hi;
                *(__nv_bfloat162*)&sTlo[r * SW_STRIDE + c0] = lo;
            }
        }
    __syncthreads();

    // ---- phase 3: out = relu(t1 @ W2^T + b2) via HMMA ----
    float acc3[2][4][4];
#pragma unroll
    for (int mi = 0; mi < 2; mi++)
#pragma unroll
        for (int q = 0; q < 4; q++)
#pragma unroll
            for (int i = 0; i < 4; i++) acc3[mi][q][i] = 0.f;
#pragma unroll
    for (int pass = 0; pass < 3; pass++) {
        const __nv_bfloat16* A = (pass == 2) ? sTlo : sThi;
        const __nv_bfloat16* B = (pass == 1) ? sWlo : sWhi;
#pragma unroll
        for (int ks = 0; ks < 4; ks++) {
            int ka = ks * 16 + 2 * tq;
            uint32_t a[2][4];
#pragma unroll
            for (int mi = 0; mi < 2; mi++) {
                const __nv_bfloat16* ar0 = A + (mb + mi * 16 + g) * SW_STRIDE + ka;
                const __nv_bfloat16* ar1 = ar0 + 8 * SW_STRIDE;
                a[mi][0] = *(const uint32_t*)ar0;
                a[mi][1] = *(const uint32_t*)ar1;
                a[mi][2] = *(const uint32_t*)(ar0 + 8);
                a[mi][3] = *(const uint32_t*)(ar1 + 8);
            }
#pragma unroll
            for (int q = 0; q < 4; q++) {
                const __nv_bfloat16* br = B + (nb + q * 8 + g) * SW_STRIDE + ka;
                uint32_t b0 = *(const uint32_t*)br;
                uint32_t b1 = *(const uint32_t*)(br + 8);
                mma_bf16(acc3[0][q], a[0][0], a[0][1], a[0][2], a[0][3], b0, b1);
                mma_bf16(acc3[1][q], a[1][0], a[1][1], a[1][2], a[1][3], b0, b1);
            }
        }
    }

    // ---- final epilogue: relu + (out write | pool accumulate) + BN stats ----
    float cs[8], cq[8];
#pragma unroll
    for (int i = 0; i < 8; i++) { cs[i] = 0.f; cq[i] = 0.f; }
#pragma unroll
    for (int mi = 0; mi < 2; mi++)
#pragma unroll
        for (int hh = 0; hh < 2; hh++) {
            int r = mb + mi * 16 + hh * 8 + g;
            int node = tileBase + r;
            if (node >= N_NODES) continue;
            int bg = (layer == 2) ? batch[node] : 0;
#pragma unroll
            for (int q = 0; q < 4; q++) {
                int c0 = nb + q * 8 + 2 * tq;
                float v0 = fmaxf(acc3[mi][q][2 * hh] + b2v[c0], 0.f);
                float v1 = fmaxf(acc3[mi][q][2 * hh + 1] + b2v[c0 + 1], 0.f);
                if (layer < 2) {
                    *(float2*)&out[node * 64 + c0] = make_float2(v0, v1);
                } else {
                    atomicAdd(&sPool[bg * 64 + c0], v0);
                    atomicAdd(&sPool[bg * 64 + c0 + 1], v1);
                }
                cs[q * 2] += v0; cs[q * 2 + 1] += v1;
                cq[q * 2] = fmaf(v0, v0, cq[q * 2]);
                cq[q * 2 + 1] = fmaf(v1, v1, cq[q * 2 + 1]);
            }
        }
#pragma unroll
    for (int q = 0; q < 4; q++)
#pragma unroll
        for (int j = 0; j < 2; j++) {
            int c = nb + q * 8 + 2 * tq + j;
            atomicAdd(&scol[c], cs[q * 2 + j]);
            atomicAdd(&scol[64 + c], cq[q * 2 + j]);
        }
    __syncthreads();
    if (t < 64) atomicAdd(&g_colsum[layer][t], scol[t]);
    else if (t < 128) atomicAdd(&g_colsq[layer][t - 64], scol[t]);
    if (layer == 2)
        for (int i = t; i < 4096; i += 256)
            if (sPool[i] != 0.f) atomicAdd(&g_pool[i], sPool[i]);
}

// ---------------- head: BN-affine pool -> fc1+relu -> fc2 -> log_softmax ----------------
__global__ __launch_bounds__(256) void k_head(const float* __restrict__ fc1W,
                                              const float* __restrict__ fc1b,
                                              const float* __restrict__ fc2W,
                                              const float* __restrict__ fc2b,
                                              const float* __restrict__ gg3,
                                              const float* __restrict__ bb3,
                                              float* __restrict__ out) {
    __shared__ float sP[4096];
    __shared__ float sab[128];
    __shared__ float sT1[4096];
    __shared__ float sT2[2048];
    int t = threadIdx.x;
    if (t < 64) {
        float m = g_colsum[2][t] * (1.f / N_NODES);
        float vv = g_colsq[2][t] * (1.f / N_NODES) - m * m;
        float a = gg3[t] * rsqrtf(vv + BN_EPS);
        sab[t] = a;
        sab[64 + t] = bb3[t] - m * a;
    }
    __syncthreads();
    for (int i = t; i < 4096; i += 256) {
        int gi = i >> 6, d = i & 63;
        sP[i] = sab[d] * g_pool[i] + sab[64 + d] * (float)g_gcnt[gi];
    }
    __syncthreads();
    for (int i = t; i < 4096; i += 256) {
        int gi = i >> 6, o = i & 63;
        float acc = fc1b[o];
        for (int k = 0; k < 64; k++) acc = fmaf(sP[gi * 64 + k], fc1W[o * 64 + k], acc);
        sT1[i] = fmaxf(acc, 0.f);
    }
    __syncthreads();
    for (int i = t; i < 2048; i += 256) {
        int gi = i >> 5, o = i & 31;
        float acc = fc2b[o];
        for (int k = 0; k < 64; k++) acc = fmaf(sT1[gi * 64 + k], fc2W[o * 64 + k], acc);
        sT2[i] = acc;
    }
    __syncthreads();
    int w = t >> 5, lane = t & 31;
    for (int gi = w; gi < 64; gi += 8) {
        float v = sT2[gi * 32 + lane];
        float mx = v;
        for (int o = 16; o > 0; o >>= 1) mx = fmaxf(mx, __shfl_xor_sync(0xffffffffu, mx, o));
        float e = expf(v - mx);
        float s = e;
        for (int o = 16; o > 0; o >>= 1) s += __shfl_xor_sync(0xffffffffu, s, o);
        out[gi * 32 + lane] = v - mx - logf(s);
    }
}

// ---------------- launch ----------------
// input order: 0:x 1:edge_index 2:batch | 3..8 c1 | 9..14 c2 | 15..20 c3 |
//              21..26 bn1_g,bn1_b,bn2_g,bn2_b,bn3_g,bn3_b | 27..30 fc
extern "C" void kernel_launch(void* const* d_in, const int* in_sizes, int n_in,
                              void* d_out, int out_size) {
    const float* x = (const float*)d_in[0];
    const int* ei = (const int*)d_in[1];
    const int* src = ei;
    const int* dst = ei + N_EDGES;
    const int* batch = (const int*)d_in[2];
    float* out = (float*)d_out;

    float *featA = nullptr, *featB = nullptr;
    cudaGetSymbolAddress((void**)&featA, g_featA);
    cudaGetSymbolAddress((void**)&featB, g_featB);

    cudaFuncSetAttribute(k_mlp, cudaFuncAttributeMaxDynamicSharedMemorySize, MLP_SMEM);

    // launch order keeps the ncu-profiled slot (index 3-4) on fill/aggr
    k_prep_all<<<(147456 + 255) / 256, 256>>>((const float*)d_in[3],      // 0
                                              (const float*)d_in[9],
                                              (const float*)d_in[15]);
    k_count<<<(N_EDGES / 4 + 255) / 256, 256>>>(dst);                      // 1
    k_scan_fused<<<NB_SCAN, 1024>>>(batch);                                // 2
    k_fill<<<(N_EDGES / 4 + 255) / 256, 256>>>(src, dst);                  // 3
    k_aggr<<<(N_NODES * 32 + 255) / 256, 256>>>(x, nullptr, nullptr, -1);  // 4
    k_prep_small<<<48, 256>>>((const float*)d_in[5], (const float*)d_in[7],// 5
                              (const float*)d_in[11], (const float*)d_in[13],
                              (const float*)d_in[17], (const float*)d_in[19]);

    const float* cur = x;
    float* nxt = featA;
    for (int L = 0; L < 3; L++) {
        const float* ggP = (L > 0) ? (const float*)d_in[21 + 2 * (L - 1)] : nullptr;
        const float* bbP = (L > 0) ? (const float*)d_in[22 + 2 * (L - 1)] : nullptr;
        if (L > 0)
            k_aggr<<<(N_NODES * 32 + 255) / 256, 256>>>(cur, ggP, bbP, L - 1);
        k_mlp<<<(N_NODES + 127) / 128, 256, MLP_SMEM>>>(cur,
                                            (const float*)d_in[4 + 6 * L],
                                            (const float*)d_in[6 + 6 * L],
                                            (const float*)d_in[8 + 6 * L],
                                            nxt, L, ggP, bbP, batch);
        cur = nxt;
        nxt = (nxt == featA) ? featB : featA;
    }

    k_head<<<1, 256>>>((const float*)d_in[27], (const float*)d_in[28],
                       (const float*)d_in[29], (const float*)d_in[30],
                       (const float*)d_in[25], (const float*)d_in[26], out);
}

// round 14
// speedup vs baseline: 1.0174x; 1.0174x over previous
#include <cuda_runtime.h>
#include <cuda_bf16.h>
#include <math.h>
#include <stdint.h>

#define N_NODES 50000
#define N_EDGES 1600000
#define N_GRAPHS 64
#define DELTA_C 2.5749f
#define BN_EPS 1e-5f
#define NB_SCAN 49

// ---------------- scratch ----------------
__device__ float g_featA[N_NODES * 64];
__device__ float g_featB[N_NODES * 64];
__device__ __nv_bfloat16 g_aggrHi[(size_t)N_NODES * 256];
__device__ __nv_bfloat16 g_aggrLo[(size_t)N_NODES * 256];
__device__ int   g_deg[N_NODES];
__device__ int   g_rowptr[N_NODES + 1];
__device__ int   g_cursor[N_NODES];
__device__ int   g_csrc[N_EDGES];
__device__ int   g_scanstate[64];
__device__ int   g_gcnt[64];
__device__ __nv_bfloat16 g_Whi[3][192 * 256];   // [p*64+o][k]
__device__ __nv_bfloat16 g_Wlo[3][192 * 256];
__device__ __nv_bfloat16 g_W1hi[3][4096], g_W1lo[3][4096];  // [o][k]
__device__ __nv_bfloat16 g_W2hi[3][4096], g_W2lo[3][4096];
__device__ float g_colsum[3][64];
__device__ float g_colsq[3][64];
__device__ float g_pool[N_GRAPHS * 64];

// smem layout for k_mlp (dynamic):
#define SA_STRIDE 264
#define SW_STRIDE 72
#define AHI_OFF 0                  // 128*264*2 = 67584
#define ALO_OFF 67584              // ends 135168
#define WHI_OFF 135168             // 27648 region
#define WLO_OFF 162816
#define MLP_SMEM 190464
// phase-2/3 overlays inside dead A region (stride 72 planes, 128x72x2 = 18432 B):
#define H_HI 0
#define H_LO 18432
#define T_HI 36864
#define T_LO 55296
#define SCOL_OFF 73728             // 128 f32
#define POOL_OFF 74240             // 4096 f32 (layer 2 only)

// scan state flags (value packed in low 30 bits)
#define FLAG_AGG (1 << 30)
#define FLAG_PRE (2 << 30)
#define VAL_MASK ((1 << 30) - 1)

// ---------------- warp mma ----------------
__device__ __forceinline__ void mma_bf16(float* acc, uint32_t a0, uint32_t a1,
                                         uint32_t a2, uint32_t a3,
                                         uint32_t b0, uint32_t b1) {
    asm volatile("mma.sync.aligned.m16n8k16.row.col.f32.bf16.bf16.f32 "
        "{%0,%1,%2,%3}, {%4,%5,%6,%7}, {%8,%9}, {%0,%1,%2,%3};"
        : "+f"(acc[0]), "+f"(acc[1]), "+f"(acc[2]), "+f"(acc[3])
        : "r"(a0), "r"(a1), "r"(a2), "r"(a3), "r"(b0), "r"(b1));
}

__device__ __forceinline__ __nv_bfloat162 bf16_split(float a, float b,
                                                     __nv_bfloat162& lo) {
    __nv_bfloat162 hi;
    hi.x = __float2bfloat16(a);
    hi.y = __float2bfloat16(b);
    lo.x = __float2bfloat16(a - __bfloat162float(hi.x));
    lo.y = __float2bfloat16(b - __bfloat162float(hi.y));
    return hi;
}

// ---------------- weight prep (all 3 layers) + zero deg/gcnt/scanstate ----------------
__global__ void k_prep_all(const float* __restrict__ W3, const float* __restrict__ W9,
                           const float* __restrict__ W15) {
    int gi = blockIdx.x * blockDim.x + threadIdx.x;
    if (gi < N_NODES) g_deg[gi] = 0;
    if (gi < 64) { g_gcnt[gi] = 0; g_scanstate[gi] = 0; }
    int layer = gi / 49152;
    int i = gi % 49152;
    if (layer < 3) {
        const float* mlpW = (layer == 0) ? W3 : (layer == 1) ? W9 : W15;
        int j = i >> 8, k = i & 255;
        int p = j >> 6, o = j & 63;
        float w = mlpW[o * 768 + p * 256 + k];
        __nv_bfloat16 hi = __float2bfloat16(w);
        __nv_bfloat16 lo = __float2bfloat16(w - __bfloat162float(hi));
        g_Whi[layer][i] = hi;
        g_Wlo[layer][i] = lo;
    }
}
__global__ void k_prep_small(const float* __restrict__ W1a, const float* __restrict__ W2a,
                             const float* __restrict__ W1b, const float* __restrict__ W2b,
                             const float* __restrict__ W1c, const float* __restrict__ W2c) {
    int gi = blockIdx.x * blockDim.x + threadIdx.x;
    int layer = gi >> 12, i = gi & 4095;
    if (layer < 3) {
        const float* W1 = (layer == 0) ? W1a : (layer == 1) ? W1b : W1c;
        const float* W2 = (layer == 0) ? W2a : (layer == 1) ? W2b : W2c;
        float w1 = W1[i], w2 = W2[i];           // [o][k] layout kept as-is
        __nv_bfloat16 h1 = __float2bfloat16(w1);
        g_W1hi[layer][i] = h1;
        g_W1lo[layer][i] = __float2bfloat16(w1 - __bfloat162float(h1));
        __nv_bfloat16 h2 = __float2bfloat16(w2);
        g_W2hi[layer][i] = h2;
        g_W2lo[layer][i] = __float2bfloat16(w2 - __bfloat162float(h2));
    }
}

// ---------------- CSR build ----------------
__global__ void k_count(const int* __restrict__ dst) {
    int e4 = blockIdx.x * blockDim.x + threadIdx.x;
    if (e4 < N_EDGES / 4) {
        int4 d = *(const int4*)&dst[e4 * 4];
        atomicAdd(&g_deg[d.x], 1);
        atomicAdd(&g_deg[d.y], 1);
        atomicAdd(&g_deg[d.z], 1);
        atomicAdd(&g_deg[d.w], 1);
    }
}

// single-kernel decoupled-lookback scan: rowptr, cursor, pool/stat zero, graph histogram
__global__ void k_scan_fused(const int* __restrict__ batch) {
    __shared__ int s[1024];
    __shared__ int s_off;
    __shared__ int h[64];
    int t = threadIdx.x, b = blockIdx.x;
    int idx = b * 1024 + t;
    if (t < 64) h[t] = 0;
    int deg = (idx < N_NODES) ? g_deg[idx] : 0;
    s[t] = deg;
    __syncthreads();
    for (int d = 1; d < 1024; d <<= 1) {
        int add = (t >= d) ? s[t - d] : 0;
        __syncthreads();
        s[t] += add;
        __syncthreads();
    }
    if (t == 0) {
        int total = s[1023];
        atomicExch(&g_scanstate[b], FLAG_AGG | total);   // publish aggregate
        int run = 0;
        for (int j = b - 1; j >= 0;) {
            int st = atomicAdd(&g_scanstate[j], 0);
            if (st == 0) continue;                        // not yet published
            if (st & FLAG_PRE) { run += st & VAL_MASK; break; }
            run += st & VAL_MASK;
            j--;
        }
        atomicExch(&g_scanstate[b], FLAG_PRE | (run + total));
        s_off = run;
    }
    __syncthreads();
    int off = s_off;
    if (idx < N_NODES) {
        int inc = off + s[t];
        g_rowptr[idx + 1] = inc;
        g_cursor[idx] = inc - deg;
        atomicAdd(&h[batch[idx]], 1);
    }
    if (idx == 0) g_rowptr[0] = 0;
    if (idx < N_GRAPHS * 64) g_pool[idx] = 0.f;
    if (idx < 192) {
        g_colsum[idx >> 6][idx & 63] = 0.f;
        g_colsq[idx >> 6][idx & 63] = 0.f;
    }
    __syncthreads();
    if (t < 64 && h[t]) atomicAdd(&g_gcnt[t], h[t]);
}

__global__ void k_fill(const int* __restrict__ src, const int* __restrict__ dst) {
    int e4 = blockIdx.x * blockDim.x + threadIdx.x;
    if (e4 < N_EDGES / 4) {
        int4 s = *(const int4*)&src[e4 * 4];
        int4 d = *(const int4*)&dst[e4 * 4];
        g_csrc[atomicAdd(&g_cursor[d.x], 1)] = s.x;
        g_csrc[atomicAdd(&g_cursor[d.y], 1)] = s.y;
        g_csrc[atomicAdd(&g_cursor[d.z], 1)] = s.z;
        g_csrc[atomicAdd(&g_cursor[d.w], 1)] = s.w;
    }
}

// ---------------- aggregation: warp/node CSR gather, fused BN affine, bf16-split out ----
__global__ __launch_bounds__(256) void k_aggr(const float* __restrict__ xf,
                                              const float* __restrict__ gg,
                                              const float* __restrict__ bb,
                                              int prevLayer) {
    int warp = (blockIdx.x * blockDim.x + threadIdx.x) >> 5;
    int lane = threadIdx.x & 31;
    if (warp >= N_NODES) return;

    float a0 = 1.f, b0 = 0.f, a1 = 1.f, b1 = 0.f;
    if (gg) {
        int c = 2 * lane;
        float m = g_colsum[prevLayer][c] * (1.f / N_NODES);
        float vv = g_colsq[prevLayer][c] * (1.f / N_NODES) - m * m;
        a0 = gg[c] * rsqrtf(vv + BN_EPS);
        b0 = bb[c] - m * a0;
        m = g_colsum[prevLayer][c + 1] * (1.f / N_NODES);
        vv = g_colsq[prevLayer][c + 1] * (1.f / N_NODES) - m * m;
        a1 = gg[c + 1] * rsqrtf(vv + BN_EPS);
        b1 = bb[c + 1] - m * a1;
    }

    int beg = g_rowptr[warp];
    int end = g_rowptr[warp + 1];

    float s0 = 0.f, s1 = 0.f, q0 = 0.f, q1 = 0.f;
    float m0 = -INFINITY, m1 = -INFINITY;

    int j = beg;
    for (; j + 32 <= end; j += 32) {
        int e = g_csrc[j + lane];
#pragma unroll
        for (int i = 0; i < 32; i++) {
            int sidx = __shfl_sync(0xffffffffu, e, i);
            float2 v = *(const float2*)&xf[sidx * 64 + 2 * lane];
            float v0 = fmaf(v.x, a0, b0);
            float v1 = fmaf(v.y, a1, b1);
            s0 += v0; s1 += v1;
            q0 = fmaf(v0, v0, q0); q1 = fmaf(v1, v1, q1);
            m0 = fmaxf(m0, v0); m1 = fmaxf(m1, v1);
        }
    }
    int nrem = end - j;
    if (nrem > 0) {
        int e = (lane < nrem) ? g_csrc[j + lane] : 0;
        for (int i = 0; i < nrem; i++) {
            int sidx = __shfl_sync(0xffffffffu, e, i);
            float2 v = *(const float2*)&xf[sidx * 64 + 2 * lane];
            float v0 = fmaf(v.x, a0, b0);
            float v1 = fmaf(v.y, a1, b1);
            s0 += v0; s1 += v1;
            q0 = fmaf(v0, v0, q0); q1 = fmaf(v1, v1, q1);
            m0 = fmaxf(m0, v0); m1 = fmaxf(m1, v1);
        }
    }

    float cnt = (float)(end - beg);
    float inv = 1.0f / cnt;
    float mean0 = s0 * inv, mean1 = s1 * inv;
    float var0 = fmaxf(q0 * inv - mean0 * mean0, 0.f);
    float var1 = fmaxf(q1 * inv - mean1 * mean1, 0.f);

    __nv_bfloat16* ah = g_aggrHi + (size_t)warp * 256;
    __nv_bfloat16* al = g_aggrLo + (size_t)warp * 256;
    __nv_bfloat162 lo, hi;
    hi = bf16_split(s0, s1, lo);
    *(__nv_bfloat162*)&ah[2 * lane] = hi;       *(__nv_bfloat162*)&al[2 * lane] = lo;
    hi = bf16_split(m0, m1, lo);
    *(__nv_bfloat162*)&ah[64 + 2 * lane] = hi;  *(__nv_bfloat162*)&al[64 + 2 * lane] = lo;
    hi = bf16_split(mean0, mean1, lo);
    *(__nv_bfloat162*)&ah[128 + 2 * lane] = hi; *(__nv_bfloat162*)&al[128 + 2 * lane] = lo;
    hi = bf16_split(var0, var1, lo);
    *(__nv_bfloat162*)&ah[192 + 2 * lane] = hi; *(__nv_bfloat162*)&al[192 + 2 * lane] = lo;
}

// ---------------- fused MLP: all three GEMMs on HMMA ----------------
__global__ __launch_bounds__(256) void k_mlp(const float* __restrict__ x,
                                             const float* __restrict__ mlpb,
                                             const float* __restrict__ b1v,
                                             const float* __restrict__ b2v,
                                             float* __restrict__ out, int layer,
                                             const float* __restrict__ ggP,
                                             const float* __restrict__ bbP,
                                             const int* __restrict__ batch) {
    extern __shared__ __align__(16) char smem[];
    __nv_bfloat16* sAhi = (__nv_bfloat16*)(smem + AHI_OFF);
    __nv_bfloat16* sAlo = (__nv_bfloat16*)(smem + ALO_OFF);
    __nv_bfloat16* sWhi = (__nv_bfloat16*)(smem + WHI_OFF);
    __nv_bfloat16* sWlo = (__nv_bfloat16*)(smem + WLO_OFF);
    __nv_bfloat16* sHhi = (__nv_bfloat16*)(smem + H_HI);
    __nv_bfloat16* sHlo = (__nv_bfloat16*)(smem + H_LO);
    __nv_bfloat16* sThi = (__nv_bfloat16*)(smem + T_HI);
    __nv_bfloat16* sTlo = (__nv_bfloat16*)(smem + T_LO);
    float* scol  = (float*)(smem + SCOL_OFF);
    float* sPool = (float*)(smem + POOL_OFF);

    int t = threadIdx.x, lane = t & 31, w = t >> 5;
    int g = lane >> 2, tq = lane & 3;
    int tileBase = blockIdx.x * 128;
    int mb = (w & 3) * 32, nb = (w >> 2) * 32;

    // ---- A copy: pre-split planes -> smem ----
    {
        int r = t >> 1;
        int half = (t & 1) * 128;
        int node = tileBase + r;
        uint4* dHi = (uint4*)(sAhi + r * SA_STRIDE + half);
        uint4* dLo = (uint4*)(sAlo + r * SA_STRIDE + half);
        if (node < N_NODES) {
            const uint4* sHi = (const uint4*)(g_aggrHi + (size_t)node * 256 + half);
            const uint4* sLo = (const uint4*)(g_aggrLo + (size_t)node * 256 + half);
#pragma unroll
            for (int c = 0; c < 16; c++) { dHi[c] = sHi[c]; dLo[c] = sLo[c]; }
        } else {
            uint4 z = make_uint4(0, 0, 0, 0);
#pragma unroll
            for (int c = 0; c < 16; c++) { dHi[c] = z; dLo[c] = z; }
        }
    }

    float acc[2][4][3][4];
#pragma unroll
    for (int mi = 0; mi < 2; mi++)
#pragma unroll
        for (int q = 0; q < 4; q++)
#pragma unroll
            for (int p = 0; p < 3; p++)
#pragma unroll
                for (int i = 0; i < 4; i++) acc[mi][q][p][i] = 0.f;

    const __nv_bfloat16* gwhi = g_Whi[layer];
    const __nv_bfloat16* gwlo = g_Wlo[layer];

    for (int kc = 0; kc < 256; kc += 64) {
        __syncthreads();
        for (int idx = t; idx < 1536; idx += 256) {
            int j = idx >> 3, kk = (idx & 7) * 8;
            *(float4*)&sWhi[j * SW_STRIDE + kk] = *(const float4*)&gwhi[j * 256 + kc + kk];
            *(float4*)&sWlo[j * SW_STRIDE + kk] = *(const float4*)&gwlo[j * 256 + kc + kk];
        }
        __syncthreads();
#pragma unroll
        for (int pass = 0; pass < 3; pass++) {
            const __nv_bfloat16* A = (pass == 2) ? sAlo : sAhi;
            const __nv_bfloat16* B = (pass == 1) ? sWlo : sWhi;
#pragma unroll
            for (int ks = 0; ks < 4; ks++) {
                int ka = kc + ks * 16 + 2 * tq;
                int kw = ks * 16 + 2 * tq;
                uint32_t a[2][4];
#pragma unroll
                for (int mi = 0; mi < 2; mi++) {
                    const __nv_bfloat16* ar0 = A + (mb + mi * 16 + g) * SA_STRIDE + ka;
                    const __nv_bfloat16* ar1 = ar0 + 8 * SA_STRIDE;
                    a[mi][0] = *(const uint32_t*)ar0;
                    a[mi][1] = *(const uint32_t*)ar1;
                    a[mi][2] = *(const uint32_t*)(ar0 + 8);
                    a[mi][3] = *(const uint32_t*)(ar1 + 8);
                }
#pragma unroll
                for (int q = 0; q < 4; q++)
#pragma unroll
                    for (int p = 0; p < 3; p++) {
                        const __nv_bfloat16* br = B + (nb + q * 8 + p * 64 + g) * SW_STRIDE + kw;
                        uint32_t b0 = *(const uint32_t*)br;
                        uint32_t b1 = *(const uint32_t*)(br + 8);
                        mma_bf16(acc[0][q][p], a[0][0], a[0][1], a[0][2], a[0][3], b0, b1);
                        mma_bf16(acc[1][q][p], a[1][0], a[1][1], a[1][2], a[1][3], b0, b1);
                    }
            }
        }
    }
    __syncthreads();   // main mma done; A region + W region reusable

    // ---- residual BN affine (layer>0) ----
    float ra[4][2], rb[4][2];
#pragma unroll
    for (int q = 0; q < 4; q++)
#pragma unroll
        for (int j = 0; j < 2; j++) {
            float a = 1.f, b = 0.f;
            if (ggP) {
                int c = nb + q * 8 + 2 * tq + j;
                float m = g_colsum[layer - 1][c] * (1.f / N_NODES);
                float vv = g_colsq[layer - 1][c] * (1.f / N_NODES) - m * m;
                a = ggP[c] * rsqrtf(vv + BN_EPS);
                b = bbP[c] - m * a;
            }
            ra[q][j] = a; rb[q][j] = b;
        }

    // ---- stream W1 planes, zero scol / sPool, split h into planes ----
    for (int i = t; i < 512; i += 256) {
        int j = i >> 3, kk = (i & 7) * 8;
        *(float4*)&sWhi[j * SW_STRIDE + kk] = *(const float4*)&g_W1hi[layer][j * 64 + kk];
        *(float4*)&sWlo[j * SW_STRIDE + kk] = *(const float4*)&g_W1lo[layer][j * 64 + kk];
    }
    if (t < 128) scol[t] = 0.f;
    if (layer == 2)
        for (int i = t; i < 4096; i += 256) sPool[i] = 0.f;

#pragma unroll
    for (int mi = 0; mi < 2; mi++)
#pragma unroll
        for (int hh = 0; hh < 2; hh++) {
            int r = mb + mi * 16 + hh * 8 + g;
            int node = tileBase + r;
            bool valid = node < N_NODES;
            float cnt = valid ? (float)g_deg[node] : 1.f;
            float s1 = cnt * (1.f / DELTA_C);
            float s2 = DELTA_C / cnt;
#pragma unroll
            for (int q = 0; q < 4; q++) {
                int c0 = nb + q * 8 + 2 * tq;
                float f0 = acc[mi][q][0][2 * hh] + s1 * acc[mi][q][1][2 * hh]
                         + s2 * acc[mi][q][2][2 * hh] + mlpb[c0];
                float f1 = acc[mi][q][0][2 * hh + 1] + s1 * acc[mi][q][1][2 * hh + 1]
                         + s2 * acc[mi][q][2][2 * hh + 1] + mlpb[c0 + 1];
                if (valid) {
                    float2 xv = *(const float2*)&x[node * 64 + c0];
                    f0 += fmaf(xv.x, ra[q][0], rb[q][0]);
                    f1 += fmaf(xv.y, ra[q][1], rb[q][1]);
                }
                __nv_bfloat162 lo, hi = bf16_split(f0, f1, lo);
                *(__nv_bfloat162*)&sHhi[r * SW_STRIDE + c0] = hi;
                *(__nv_bfloat162*)&sHlo[r * SW_STRIDE + c0] = lo;
            }
        }
    __syncthreads();

    // ---- phase 2: t1 = relu(h @ W1^T + b1) via HMMA (K=64) ----
    float acc2[2][4][4];
#pragma unroll
    for (int mi = 0; mi < 2; mi++)
#pragma unroll
        for (int q = 0; q < 4; q++)
#pragma unroll
            for (int i = 0; i < 4; i++) acc2[mi][q][i] = 0.f;
#pragma unroll
    for (int pass = 0; pass < 3; pass++) {
        const __nv_bfloat16* A = (pass == 2) ? sHlo : sHhi;
        const __nv_bfloat16* B = (pass == 1) ? sWlo : sWhi;
#pragma unroll
        for (int ks = 0; ks < 4; ks++) {
            int ka = ks * 16 + 2 * tq;
            uint32_t a[2][4];
#pragma unroll
            for (int mi = 0; mi < 2; mi++) {
                const __nv_bfloat16* ar0 = A + (mb + mi * 16 + g) * SW_STRIDE + ka;
                const __nv_bfloat16* ar1 = ar0 + 8 * SW_STRIDE;
                a[mi][0] = *(const uint32_t*)ar0;
                a[mi][1] = *(const uint32_t*)ar1;
                a[mi][2] = *(const uint32_t*)(ar0 + 8);
                a[mi][3] = *(const uint32_t*)(ar1 + 8);
            }
#pragma unroll
            for (int q = 0; q < 4; q++) {
                const __nv_bfloat16* br = B + (nb + q * 8 + g) * SW_STRIDE + ka;
                uint32_t b0 = *(const uint32_t*)br;
                uint32_t b1 = *(const uint32_t*)(br + 8);
                mma_bf16(acc2[0][q], a[0][0], a[0][1], a[0][2], a[0][3], b0, b1);
                mma_bf16(acc2[1][q], a[1][0], a[1][1], a[1][2], a[1][3], b0, b1);
            }
        }
    }
    __syncthreads();   // W1 reads done -> stream W2

    for (int i = t; i < 512; i += 256) {
        int j = i >> 3, kk = (i & 7) * 8;
        *(float4*)&sWhi[j * SW_STRIDE + kk] = *(const float4*)&g_W2hi[layer][j * 64 + kk];
        *(float4*)&sWlo[j * SW_STRIDE + kk] = *(const float4*)&g_W2lo[layer][j * 64 + kk];
    }
#pragma unroll
    for (int mi = 0; mi < 2; mi++)
#pragma unroll
        for (int hh = 0; hh < 2; hh++) {
            int r = mb + mi * 16 + hh * 8 + g;
#pragma unroll
            for (int q = 0; q < 4; q++) {
                int c0 = nb + q * 8 + 2 * tq;
                float v0 = fmaxf(acc2[mi][q][2 * hh] + b1v[c0], 0.f);
                float v1 = fmaxf(acc2[mi][q][2 * hh + 1] + b1v[c0 + 1], 0.f);
                __nv_bfloat162 lo, hi = bf16_split(v0, v1, lo);
                *(__nv_bfloat162*)&sThi[r * SW_STRIDE + c0] = hi;
                *(__nv_bfloat162*)&sTlo[r * SW_STRIDE + c0] = lo;
            }
        }
    __syncthreads();

    // ---- phase 3: out = relu(t1 @ W2^T + b2) via HMMA ----
    float acc3[2][4][4];
#pragma unroll
    for (int mi = 0; mi < 2; mi++)
#pragma unroll
        for (int q = 0; q < 4; q++)
#pragma unroll
            for (int i = 0; i < 4; i++) acc3[mi][q][i] = 0.f;
#pragma unroll
    for (int pass = 0; pass < 3; pass++) {
        const __nv_bfloat16* A = (pass == 2) ? sTlo : sThi;
        const __nv_bfloat16* B = (pass == 1) ? sWlo : sWhi;
#pragma unroll
        for (int ks = 0; ks < 4; ks++) {
            int ka = ks * 16 + 2 * tq;
            uint32_t a[2][4];
#pragma unroll
            for (int mi = 0; mi < 2; mi++) {
                const __nv_bfloat16* ar0 = A + (mb + mi * 16 + g) * SW_STRIDE + ka;
                const __nv_bfloat16* ar1 = ar0 + 8 * SW_STRIDE;
                a[mi][0] = *(const uint32_t*)ar0;
                a[mi][1] = *(const uint32_t*)ar1;
                a[mi][2] = *(const uint32_t*)(ar0 + 8);
                a[mi][3] = *(const uint32_t*)(ar1 + 8);
            }
#pragma unroll
            for (int q = 0; q < 4; q++) {
                const __nv_bfloat16* br = B + (nb + q * 8 + g) * SW_STRIDE + ka;
                uint32_t b0 = *(const uint32_t*)br;
                uint32_t b1 = *(const uint32_t*)(br + 8);
                mma_bf16(acc3[0][q], a[0][0], a[0][1], a[0][2], a[0][3], b0, b1);
                mma_bf16(acc3[1][q], a[1][0], a[1][1], a[1][2], a[1][3], b0, b1);
            }
        }
    }

    // ---- final epilogue: relu + (out write | pool accumulate) + BN stats ----
    float cs[8], cq[8];
#pragma unroll
    for (int i = 0; i < 8; i++) { cs[i] = 0.f; cq[i] = 0.f; }
#pragma unroll
    for (int mi = 0; mi < 2; mi++)
#pragma unroll
        for (int hh = 0; hh < 2; hh++) {
            int r = mb + mi * 16 + hh * 8 + g;
            int node = tileBase + r;
            if (node >= N_NODES) continue;
            int bg = (layer == 2) ? batch[node] : 0;
#pragma unroll
            for (int q = 0; q < 4; q++) {
                int c0 = nb + q * 8 + 2 * tq;
                float v0 = fmaxf(acc3[mi][q][2 * hh] + b2v[c0], 0.f);
                float v1 = fmaxf(acc3[mi][q][2 * hh + 1] + b2v[c0 + 1], 0.f);
                if (layer < 2) {
                    *(float2*)&out[node * 64 + c0] = make_float2(v0, v1);
                } else {
                    atomicAdd(&sPool[bg * 64 + c0], v0);
                    atomicAdd(&sPool[bg * 64 + c0 + 1], v1);
                }
                cs[q * 2] += v0; cs[q * 2 + 1] += v1;
                cq[q * 2] = fmaf(v0, v0, cq[q * 2]);
                cq[q * 2 + 1] = fmaf(v1, v1, cq[q * 2 + 1]);
            }
        }
#pragma unroll
    for (int q = 0; q < 4; q++)
#pragma unroll
        for (int j = 0; j < 2; j++) {
            int c = nb + q * 8 + 2 * tq + j;
            atomicAdd(&scol[c], cs[q * 2 + j]);
            atomicAdd(&scol[64 + c], cq[q * 2 + j]);
        }
    __syncthreads();
    if (t < 64) atomicAdd(&g_colsum[layer][t], scol[t]);
    else if (t < 128) atomicAdd(&g_colsq[layer][t - 64], scol[t]);
    if (layer == 2)
        for (int i = t; i < 4096; i += 256)
            if (sPool[i] != 0.f) atomicAdd(&g_pool[i], sPool[i]);
}

// ---------------- head: BN-affine pool -> fc1+relu -> fc2 -> log_softmax ----------------
__global__ __launch_bounds__(256) void k_head(const float* __restrict__ fc1W,
                                              const float* __restrict__ fc1b,
                                              const float* __restrict__ fc2W,
                                              const float* __restrict__ fc2b,
                                              const float* __restrict__ gg3,
                                              const float* __restrict__ bb3,
                                              float* __restrict__ out) {
    __shared__ float sP[4096];
    __shared__ float sab[128];
    __shared__ float sT1[4096];
    __shared__ float sT2[2048];
    int t = threadIdx.x;
    if (t < 64) {
        float m = g_colsum[2][t] * (1.f / N_NODES);
        float vv = g_colsq[2][t] * (1.f / N_NODES) - m * m;
        float a = gg3[t] * rsqrtf(vv + BN_EPS);
        sab[t] = a;
        sab[64 + t] = bb3[t] - m * a;
    }
    __syncthreads();
    for (int i = t; i < 4096; i += 256) {
        int gi = i >> 6, d = i & 63;
        sP[i] = sab[d] * g_pool[i] + sab[64 + d] * (float)g_gcnt[gi];
    }
    __syncthreads();
    for (int i = t; i < 4096; i += 256) {
        int gi = i >> 6, o = i & 63;
        float acc = fc1b[o];
        for (int k = 0; k < 64; k++) acc = fmaf(sP[gi * 64 + k], fc1W[o * 64 + k], acc);
        sT1[i] = fmaxf(acc, 0.f);
    }
    __syncthreads();
    for (int i = t; i < 2048; i += 256) {
        int gi = i >> 5, o = i & 31;
        float acc = fc2b[o];
        for (int k = 0; k < 64; k++) acc = fmaf(sT1[gi * 64 + k], fc2W[o * 64 + k], acc);
        sT2[i] = acc;
    }
    __syncthreads();
    int w = t >> 5, lane = t & 31;
    for (int gi = w; gi < 64; gi += 8) {
        float v = sT2[gi * 32 + lane];
        float mx = v;
        for (int o = 16; o > 0; o >>= 1) mx = fmaxf(mx, __shfl_xor_sync(0xffffffffu, mx, o));
        float e = expf(v - mx);
        float s = e;
        for (int o = 16; o > 0; o >>= 1) s += __shfl_xor_sync(0xffffffffu, s, o);
        out[gi * 32 + lane] = v - mx - logf(s);
    }
}

// ---------------- launch ----------------
// input order: 0:x 1:edge_index 2:batch | 3..8 c1 | 9..14 c2 | 15..20 c3 |
//              21..26 bn1_g,bn1_b,bn2_g,bn2_b,bn3_g,bn3_b | 27..30 fc
extern "C" void kernel_launch(void* const* d_in, const int* in_sizes, int n_in,
                              void* d_out, int out_size) {
    const float* x = (const float*)d_in[0];
    const int* ei = (const int*)d_in[1];
    const int* src = ei;
    const int* dst = ei + N_EDGES;
    const int* batch = (const int*)d_in[2];
    float* out = (float*)d_out;

    float *featA = nullptr, *featB = nullptr;
    cudaGetSymbolAddress((void**)&featA, g_featA);
    cudaGetSymbolAddress((void**)&featB, g_featB);

    cudaFuncSetAttribute(k_mlp, cudaFuncAttributeMaxDynamicSharedMemorySize, MLP_SMEM);

    // launch order keeps the ncu-profiled slot (index 3-4) on fill/aggr
    k_prep_all<<<(147456 + 255) / 256, 256>>>((const float*)d_in[3],      // 0
                                              (const float*)d_in[9],
                                              (const float*)d_in[15]);
    k_count<<<(N_EDGES / 4 + 255) / 256, 256>>>(dst);                      // 1
    k_scan_fused<<<NB_SCAN, 1024>>>(batch);                                // 2
    k_fill<<<(N_EDGES / 4 + 255) / 256, 256>>>(src, dst);                  // 3
    k_aggr<<<(N_NODES * 32 + 255) / 256, 256>>>(x, nullptr, nullptr, -1);  // 4
    k_prep_small<<<48, 256>>>((const float*)d_in[5], (const float*)d_in[7],// 5
                              (const float*)d_in[11], (const float*)d_in[13],
                              (const float*)d_in[17], (const float*)d_in[19]);

    const float* cur = x;
    float* nxt = featA;
    for (int L = 0; L < 3; L++) {
        const float* ggP = (L > 0) ? (const float*)d_in[21 + 2 * (L - 1)] : nullptr;
        const float* bbP = (L > 0) ? (const float*)d_in[22 + 2 * (L - 1)] : nullptr;
        if (L > 0)
            k_aggr<<<(N_NODES * 32 + 255) / 256, 256>>>(cur, ggP, bbP, L - 1);
        k_mlp<<<(N_NODES + 127) / 128, 256, MLP_SMEM>>>(cur,
                                            (const float*)d_in[4 + 6 * L],
                                            (const float*)d_in[6 + 6 * L],
                                            (const float*)d_in[8 + 6 * L],
                                            nxt, L, ggP, bbP, batch);
        cur = nxt;
        nxt = (nxt == featA) ? featB : featA;
    }

    k_head<<<1, 256>>>((const float*)d_in[27], (const float*)d_in[28],
                       (const float*)d_in[29], (const float*)d_in[30],
                       (const float*)d_in[25], (const float*)d_in[26], out);
}